// round 3
// baseline (speedup 1.0000x reference)
#include <cuda_runtime.h>
#include <stdint.h>

// ---------------- problem constants ----------------
#define KDIM 30000
#define MDIM 3200            // B*L
#define NDIM 1000            // Co
#define NPAD 1024
#define BDIM 32
#define CDIM 104
#define NPOOL 10

// ---------------- GEMM tiling ----------------
#define MT 128
#define NT 128
#define KB 32
#define KSPLIT 2
#define KLEN (KDIM / KSPLIT)              // 15000
#define ITERS ((KLEN + KB - 1) / KB)      // 469 (tail 24, cp.async zero-fills)
#define STAGES 3
#define RSTRIDE 36                        // padded row stride (bank-conflict-free frags)
#define STAGE_FLOATS ((MT + NT) * RSTRIDE)    // 9216
#define STAGE_BYTES (STAGE_FLOATS * 4)        // 36864
#define SMEM_BYTES (STAGES * STAGE_BYTES)     // 110592 -> occupancy 2 w/ 256 thr

// ---------------- static scratch ----------------
__device__ float g_part[KSPLIT][(size_t)MDIM * NPAD];  // K-split partial sums
__device__ float g_pool[BDIM * NDIM * NPOOL];
__device__ float g_ss[BDIM * 4];                        // partial sum-of-squares

// ---------------- helpers ----------------
static __device__ __forceinline__ uint32_t smem_u32(const void* p) {
    uint32_t a;
    asm("{ .reg .u64 t; cvta.to.shared.u64 t, %1; cvt.u32.u64 %0, t; }" : "=r"(a) : "l"(p));
    return a;
}
static __device__ __forceinline__ void cp_async16(uint32_t saddr, const float* gptr, uint32_t sz) {
    asm volatile("cp.async.cg.shared.global [%0], [%1], 16, %2;"
                 :: "r"(saddr), "l"(gptr), "r"(sz) : "memory");
}
static __device__ __forceinline__ void cp_commit() {
    asm volatile("cp.async.commit_group;" ::: "memory");
}
static __device__ __forceinline__ void cp_wait1() {
    asm volatile("cp.async.wait_group 1;" ::: "memory");
}
// load fp32 from smem and round to tf32-canonical (rna) in one step
static __device__ __forceinline__ uint32_t lds_tf32(const float* p) {
    uint32_t u;
    float f = *p;
    asm("cvt.rna.tf32.f32 %0, %1;" : "=r"(u) : "f"(f));
    return u;
}

#define MMA_TF32(d, a, b)                                                          \
    asm volatile(                                                                  \
        "mma.sync.aligned.m16n8k8.row.col.f32.tf32.tf32.f32 "                      \
        "{%0,%1,%2,%3}, {%4,%5,%6,%7}, {%8,%9}, {%0,%1,%2,%3};"                    \
        : "+f"((d)[0]), "+f"((d)[1]), "+f"((d)[2]), "+f"((d)[3])                   \
        : "r"((a)[0]), "r"((a)[1]), "r"((a)[2]), "r"((a)[3]),                      \
          "r"((b)[0]), "r"((b)[1]))

// =====================================================================
// Kernel 1: GEMM partial[z][m][n] = sum_{k in split z} x[m,k]*w[n,k]
// CTA 128x128, 8 warps of 64x32, tf32 mma.sync, 3-stage cp.async,
// fp32->tf32 rounding done on fragments in-register.
// grid (25, 8), block 256, one launch per K-split z.
// =====================================================================
__global__ void __launch_bounds__(256, 2)
gemm_kernel(const float* __restrict__ x, const float* __restrict__ w, int z) {
    extern __shared__ float sm[];
    const int tid = threadIdx.x;
    const int wid = tid >> 5;
    const int lane = tid & 31;
    const int g = lane >> 2;        // groupID (row within 8)
    const int tig = lane & 3;       // thread in group (col pair)
    const int wm = wid >> 2;        // 0..1 (64-row slab)
    const int wn = wid & 3;         // 0..3 (32-col slab)
    const int m0 = blockIdx.x * MT;
    const int n0 = blockIdx.y * NT;
    const uint32_t sbase = smem_u32(sm);

    // ---- per-thread cp.async items (8 items: 256 rows x 8 slots of 16B) ----
    const float* gp[8];
    uint32_t soff[8];
    int slot4[8];
    uint32_t rowok[8];
    #pragma unroll
    for (int u = 0; u < 8; ++u) {
        int i = tid + u * 256;
        int row = i >> 3;
        int slot = i & 7;
        const float* base;
        uint32_t ok = 1;
        if (row < MT) {
            base = x + (size_t)(m0 + row) * KDIM;
        } else {
            int n = n0 + row - MT;
            if (n >= NDIM) { n = NDIM - 1; ok = 0; }
            base = w + (size_t)n * KDIM;
        }
        gp[u] = base + (size_t)z * KLEN + slot * 4;
        soff[u] = (uint32_t)(row * RSTRIDE + slot * 4) * 4u;
        slot4[u] = slot * 4;
        rowok[u] = ok;
    }

    #define ISSUE(it)                                                              \
        do {                                                                       \
            const int kb = (it) * KB;                                              \
            const int kleft = KLEN - kb;                                           \
            const uint32_t stb = sbase + ((it) % STAGES) * STAGE_BYTES;            \
            _Pragma("unroll")                                                      \
            for (int u = 0; u < 8; ++u) {                                          \
                int rem = kleft - slot4[u];                                        \
                uint32_t sz = 0u;                                                  \
                if (rowok[u] && rem > 0) sz = rem >= 4 ? 16u : (uint32_t)rem * 4u; \
                cp_async16(stb + soff[u], gp[u] + kb, sz);                         \
            }                                                                      \
        } while (0)

    // ---- prologue ----
    ISSUE(0); cp_commit();
    ISSUE(1); cp_commit();

    // ---- accumulators: warp tile 64x32 = 4x4 mma tiles ----
    float acc[4][4][4];
    #pragma unroll
    for (int mt = 0; mt < 4; ++mt)
        #pragma unroll
        for (int nt = 0; nt < 4; ++nt)
            #pragma unroll
            for (int r = 0; r < 4; ++r) acc[mt][nt][r] = 0.f;

    const int a_row0 = wm * 64 + g;
    const int b_row0 = wn * 32 + g;

    // ---- main loop ----
    for (int it = 0; it < ITERS; ++it) {
        cp_wait1();
        __syncthreads();
        if (it + 2 < ITERS) { ISSUE(it + 2); }
        cp_commit();

        const float* As = sm + (it % STAGES) * STAGE_FLOATS;
        const float* Bs = As + MT * RSTRIDE;

        #pragma unroll
        for (int ks = 0; ks < 4; ++ks) {
            const int kc = ks * 8 + tig;
            uint32_t af[4][4];
            #pragma unroll
            for (int mt = 0; mt < 4; ++mt) {
                const float* p = As + (a_row0 + mt * 16) * RSTRIDE + kc;
                af[mt][0] = lds_tf32(p);
                af[mt][1] = lds_tf32(p + 8 * RSTRIDE);
                af[mt][2] = lds_tf32(p + 4);
                af[mt][3] = lds_tf32(p + 8 * RSTRIDE + 4);
            }
            uint32_t bf[4][2];
            #pragma unroll
            for (int nt = 0; nt < 4; ++nt) {
                const float* p = Bs + (b_row0 + nt * 8) * RSTRIDE + kc;
                bf[nt][0] = lds_tf32(p);
                bf[nt][1] = lds_tf32(p + 4);
            }
            #pragma unroll
            for (int mt = 0; mt < 4; ++mt)
                #pragma unroll
                for (int nt = 0; nt < 4; ++nt)
                    MMA_TF32(acc[mt][nt], af[mt], bf[nt]);
        }
    }

    // ---- epilogue: store partials (padded N dim => no predication) ----
    float* dst = &g_part[z][0];
    #pragma unroll
    for (int mt = 0; mt < 4; ++mt) {
        const int r0 = m0 + wm * 64 + mt * 16 + g;
        #pragma unroll
        for (int nt = 0; nt < 4; ++nt) {
            const int c = n0 + wn * 32 + nt * 8 + 2 * tig;
            *(float2*)&dst[(size_t)r0 * NPAD + c] =
                make_float2(acc[mt][nt][0], acc[mt][nt][1]);
            *(float2*)&dst[(size_t)(r0 + 8) * NPAD + c] =
                make_float2(acc[mt][nt][2], acc[mt][nt][3]);
        }
    }
    #undef ISSUE
}

// =====================================================================
// Kernel 2: bias + relu + avg-pool(10) + partial sum-of-squares
// grid (4, 32): blockIdx.x = channel quarter, blockIdx.y = batch
// =====================================================================
__global__ void __launch_bounds__(256) pool_norm_kernel(const float* __restrict__ conv_b) {
    const int q = blockIdx.x;
    const int b = blockIdx.y;
    const int tid = threadIdx.x;
    __shared__ float red[256];

    float ss = 0.f;
    if (tid < 250) {
        const int o = q * 250 + tid;
        const float bias = conv_b[o];
        float* pb = g_pool + (size_t)b * (NDIM * NPOOL) + o * NPOOL;
        #pragma unroll 2
        for (int p = 0; p < NPOOL; ++p) {
            float acc = 0.f;
            #pragma unroll
            for (int i = 0; i < 10; ++i) {
                const size_t m = (size_t)(b * 100 + p * 10 + i) * NPAD + o;
                acc += fmaxf(g_part[0][m] + g_part[1][m] + bias, 0.f);
            }
            const float v = acc * 0.1f;
            pb[p] = v;
            ss += v * v;
        }
    }
    red[tid] = ss;
    __syncthreads();
    for (int st = 128; st > 0; st >>= 1) {
        if (tid < st) red[tid] += red[tid + st];
        __syncthreads();
    }
    if (tid == 0) g_ss[b * 4 + q] = red[0];
}

// =====================================================================
// Kernel 3: logits (folds the normalization)
// =====================================================================
__global__ void __launch_bounds__(256) fc_kernel(const float* __restrict__ fc_w,
                                                 const float* __restrict__ fc_b,
                                                 float* __restrict__ out) {
    const int c = blockIdx.x;
    const int wid = threadIdx.x >> 5;
    const int lane = threadIdx.x & 31;
    const float4* wrow = (const float4*)(fc_w + (size_t)c * (NDIM * NPOOL));

    for (int b = wid; b < BDIM; b += 8) {
        const float4* pr = (const float4*)(g_pool + (size_t)b * (NDIM * NPOOL));
        float acc = 0.f;
        for (int k = lane; k < (NDIM * NPOOL) / 4; k += 32) {
            float4 w4 = wrow[k];
            float4 p4 = pr[k];
            acc += w4.x * p4.x + w4.y * p4.y + w4.z * p4.z + w4.w * p4.w;
        }
        #pragma unroll
        for (int off = 16; off > 0; off >>= 1)
            acc += __shfl_xor_sync(0xFFFFFFFFu, acc, off);
        if (lane == 0) {
            const float ss = g_ss[b * 4 + 0] + g_ss[b * 4 + 1] +
                             g_ss[b * 4 + 2] + g_ss[b * 4 + 3];
            out[b * CDIM + c] = fc_b[c] + rsqrtf(1.0f + ss) * acc;
        }
    }
}

// =====================================================================
extern "C" void kernel_launch(void* const* d_in, const int* in_sizes, int n_in,
                              void* d_out, int out_size) {
    const float* x      = (const float*)d_in[0];  // [32,100,30000]
    const float* conv_w = (const float*)d_in[1];  // [1000,30000]
    const float* conv_b = (const float*)d_in[2];  // [1000]
    const float* fc_w   = (const float*)d_in[3];  // [104,10000]
    const float* fc_b   = (const float*)d_in[4];  // [104]
    float* out = (float*)d_out;                   // [32,104]

    static int configured = 0;
    if (!configured) {
        cudaFuncSetAttribute(gemm_kernel,
                             cudaFuncAttributeMaxDynamicSharedMemorySize, SMEM_BYTES);
        configured = 1;
    }

    gemm_kernel<<<dim3(MDIM / MT, NDIM / NT + (NDIM % NT ? 1 : 0)), 256, SMEM_BYTES>>>(x, conv_w, 0);
    gemm_kernel<<<dim3(MDIM / MT, NDIM / NT + (NDIM % NT ? 1 : 0)), 256, SMEM_BYTES>>>(x, conv_w, 1);
    pool_norm_kernel<<<dim3(4, BDIM), 256>>>(conv_b);
    fc_kernel<<<CDIM, 256>>>(fc_w, fc_b, out);
}

// round 4
// speedup vs baseline: 3.9897x; 3.9897x over previous
#include <cuda_runtime.h>
#include <cuda_fp16.h>
#include <stdint.h>

// ---------------- problem constants ----------------
#define KDIM 30000
#define MDIM 3200            // B*L
#define NDIM 1000            // Co
#define NPAD 1024
#define BDIM 32
#define CDIM 104
#define NPOOL 10

// ---------------- GEMM tiling (fp16 mma m16n8k16) ----------------
#define MT 128
#define NT 128
#define KB 64                             // halves per stage
#define KSPLIT 2
#define KLEN (KDIM / KSPLIT)              // 15000
#define ITERS ((KLEN + KB - 1) / KB)      // 235 (tail 24 halves = 3 full 16B slots)
#define STAGES 3
#define S 72                              // padded row stride in halves (conflict-free)
#define STAGE_HALVES ((MT + NT) * S)      // 18432
#define STAGE_BYTES (STAGE_HALVES * 2)    // 36864
#define SMEM_BYTES (STAGES * STAGE_BYTES) // 110592 -> occ 2 with 128 threads

// ---------------- static scratch ----------------
__device__ __half g_xh[(size_t)MDIM * KDIM];           // fp16 x
__device__ __half g_wh[(size_t)NDIM * KDIM];           // fp16 conv_w
__device__ float g_part[KSPLIT][(size_t)MDIM * NPAD];  // K-split partials
__device__ float g_pool[BDIM * NDIM * NPOOL];
__device__ float g_ss[BDIM * 4];                       // partial sum-of-squares
__device__ float g_fcp[4][BDIM][CDIM];                 // fc K-split partials

// ---------------- helpers ----------------
static __device__ __forceinline__ uint32_t smem_u32(const void* p) {
    uint32_t a;
    asm("{ .reg .u64 t; cvta.to.shared.u64 t, %1; cvt.u32.u64 %0, t; }" : "=r"(a) : "l"(p));
    return a;
}
static __device__ __forceinline__ void cp_async16(uint32_t saddr, const void* gptr, uint32_t sz) {
    asm volatile("cp.async.cg.shared.global [%0], [%1], 16, %2;"
                 :: "r"(saddr), "l"(gptr), "r"(sz) : "memory");
}
static __device__ __forceinline__ void cp_commit() {
    asm volatile("cp.async.commit_group;" ::: "memory");
}
static __device__ __forceinline__ void cp_wait1() {
    asm volatile("cp.async.wait_group 1;" ::: "memory");
}

#define MMA_F16(d, a, b)                                                           \
    asm volatile(                                                                  \
        "mma.sync.aligned.m16n8k16.row.col.f32.f16.f16.f32 "                       \
        "{%0,%1,%2,%3}, {%4,%5,%6,%7}, {%8,%9}, {%0,%1,%2,%3};"                    \
        : "+f"((d)[0]), "+f"((d)[1]), "+f"((d)[2]), "+f"((d)[3])                   \
        : "r"((a)[0]), "r"((a)[1]), "r"((a)[2]), "r"((a)[3]),                      \
          "r"((b)[0]), "r"((b)[1]))

// =====================================================================
// Kernel 0: fp32 -> fp16 (rn). 8 floats -> one 16B store per thread-step.
// =====================================================================
__global__ void __launch_bounds__(256) convert_kernel(const float* __restrict__ src,
                                                      __half* __restrict__ dst, int n8) {
    int i = blockIdx.x * blockDim.x + threadIdx.x;
    const int stride = gridDim.x * blockDim.x;
    for (; i < n8; i += stride) {
        float4 v0 = ((const float4*)src)[i * 2];
        float4 v1 = ((const float4*)src)[i * 2 + 1];
        __half2 h0 = __floats2half2_rn(v0.x, v0.y);
        __half2 h1 = __floats2half2_rn(v0.z, v0.w);
        __half2 h2 = __floats2half2_rn(v1.x, v1.y);
        __half2 h3 = __floats2half2_rn(v1.z, v1.w);
        uint4 o;
        o.x = *(uint32_t*)&h0; o.y = *(uint32_t*)&h1;
        o.z = *(uint32_t*)&h2; o.w = *(uint32_t*)&h3;
        ((uint4*)dst)[i] = o;
    }
}

// =====================================================================
// Kernel 1: GEMM partial[z][m][n] = sum_{k in split z} x[m,k]*w[n,k]
// fp16 mma.sync m16n8k16, CTA 128x128, 4 warps of 64x64, 3-stage cp.async.
// grid (25, 8, 2), block 128.
// =====================================================================
__global__ void __launch_bounds__(128, 2)
gemm_kernel() {
    extern __shared__ __half sm[];
    const int tid = threadIdx.x;
    const int wid = tid >> 5;
    const int lane = tid & 31;
    const int g = lane >> 2;        // groupID
    const int tig = lane & 3;       // thread in group
    const int wm = wid >> 1;        // 0..1
    const int wn = wid & 1;         // 0..1
    const int m0 = blockIdx.x * MT;
    const int n0 = blockIdx.y * NT;
    const int z = blockIdx.z;
    const uint32_t sbase = smem_u32(sm);

    // ---- per-thread cp.async items (16: 256 rows x 8 slots of 8 halves) ----
    const __half* gp[16];
    uint32_t soff[16];
    int slot8[16];
    uint32_t rowok[16];
    #pragma unroll
    for (int u = 0; u < 16; ++u) {
        int i = tid + u * 128;
        int row = i >> 3;
        int slot = i & 7;
        const __half* base;
        uint32_t ok = 1;
        if (row < MT) {
            base = g_xh + (size_t)(m0 + row) * KDIM;
        } else {
            int n = n0 + row - MT;
            if (n >= NDIM) { n = NDIM - 1; ok = 0; }
            base = g_wh + (size_t)n * KDIM;
        }
        gp[u] = base + (size_t)z * KLEN + slot * 8;
        soff[u] = (uint32_t)(row * S + slot * 8) * 2u;
        slot8[u] = slot * 8;
        rowok[u] = ok;
    }

    // tail = 24 halves = exactly 3 full 16B slots -> sz is always 16 or 0
    #define ISSUE(it)                                                              \
        do {                                                                       \
            const int kb = (it) * KB;                                              \
            const int kleft = KLEN - kb;                                           \
            const uint32_t stb = sbase + ((it) % STAGES) * STAGE_BYTES;            \
            _Pragma("unroll")                                                      \
            for (int u = 0; u < 16; ++u) {                                         \
                uint32_t sz = (rowok[u] && slot8[u] < kleft) ? 16u : 0u;           \
                cp_async16(stb + soff[u], gp[u] + kb, sz);                         \
            }                                                                      \
        } while (0)

    // ---- prologue ----
    ISSUE(0); cp_commit();
    ISSUE(1); cp_commit();

    // ---- accumulators: warp tile 64x64 = 4x8 mma tiles ----
    float acc[4][8][4];
    #pragma unroll
    for (int mt = 0; mt < 4; ++mt)
        #pragma unroll
        for (int nt = 0; nt < 8; ++nt)
            #pragma unroll
            for (int r = 0; r < 4; ++r) acc[mt][nt][r] = 0.f;

    const int a_row0 = wm * 64 + g;
    const int b_row0 = wn * 64 + g;

    // ---- main loop ----
    for (int it = 0; it < ITERS; ++it) {
        cp_wait1();
        __syncthreads();
        if (it + 2 < ITERS) { ISSUE(it + 2); }
        cp_commit();

        const __half* As = sm + ((size_t)(it % STAGES)) * STAGE_HALVES;
        const __half* Bs = As + MT * S;

        #pragma unroll
        for (int ks = 0; ks < 4; ++ks) {
            const int kc = ks * 16 + 2 * tig;
            uint32_t af[4][4];
            #pragma unroll
            for (int mt = 0; mt < 4; ++mt) {
                const __half* p = As + (a_row0 + mt * 16) * S + kc;
                af[mt][0] = *(const uint32_t*)(p);
                af[mt][1] = *(const uint32_t*)(p + 8 * S);
                af[mt][2] = *(const uint32_t*)(p + 8);
                af[mt][3] = *(const uint32_t*)(p + 8 * S + 8);
            }
            uint32_t bf[8][2];
            #pragma unroll
            for (int nt = 0; nt < 8; ++nt) {
                const __half* p = Bs + (b_row0 + nt * 8) * S + kc;
                bf[nt][0] = *(const uint32_t*)(p);
                bf[nt][1] = *(const uint32_t*)(p + 8);
            }
            #pragma unroll
            for (int mt = 0; mt < 4; ++mt)
                #pragma unroll
                for (int nt = 0; nt < 8; ++nt)
                    MMA_F16(acc[mt][nt], af[mt], bf[nt]);
        }
    }

    // ---- epilogue: store partials (padded N => no predication) ----
    float* dst = &g_part[z][0];
    #pragma unroll
    for (int mt = 0; mt < 4; ++mt) {
        const int r0 = m0 + wm * 64 + mt * 16 + g;
        #pragma unroll
        for (int nt = 0; nt < 8; ++nt) {
            const int c = n0 + wn * 64 + nt * 8 + 2 * tig;
            *(float2*)&dst[(size_t)r0 * NPAD + c] =
                make_float2(acc[mt][nt][0], acc[mt][nt][1]);
            *(float2*)&dst[(size_t)(r0 + 8) * NPAD + c] =
                make_float2(acc[mt][nt][2], acc[mt][nt][3]);
        }
    }
    #undef ISSUE
}

// =====================================================================
// Kernel 2: bias + relu + avg-pool(10) + partial sum-of-squares
// grid (4, 32): blockIdx.x = channel quarter, blockIdx.y = batch
// =====================================================================
__global__ void __launch_bounds__(256) pool_norm_kernel(const float* __restrict__ conv_b) {
    const int q = blockIdx.x;
    const int b = blockIdx.y;
    const int tid = threadIdx.x;
    __shared__ float red[256];

    float ss = 0.f;
    if (tid < 250) {
        const int o = q * 250 + tid;
        const float bias = conv_b[o];
        float* pb = g_pool + (size_t)b * (NDIM * NPOOL) + o * NPOOL;
        #pragma unroll 2
        for (int p = 0; p < NPOOL; ++p) {
            float acc = 0.f;
            #pragma unroll
            for (int i = 0; i < 10; ++i) {
                const size_t m = (size_t)(b * 100 + p * 10 + i) * NPAD + o;
                acc += fmaxf(g_part[0][m] + g_part[1][m] + bias, 0.f);
            }
            const float v = acc * 0.1f;
            pb[p] = v;
            ss += v * v;
        }
    }
    red[tid] = ss;
    __syncthreads();
    for (int st = 128; st > 0; st >>= 1) {
        if (tid < st) red[tid] += red[tid + st];
        __syncthreads();
    }
    if (tid == 0) g_ss[b * 4 + q] = red[0];
}

// =====================================================================
// Kernel 3a: fc partials — grid (104, 4), block 128 (4 warps x 8 batches)
// each block: class c, K-quarter z (2500 floats)
// =====================================================================
__global__ void __launch_bounds__(128) fc_partial_kernel(const float* __restrict__ fc_w) {
    const int c = blockIdx.x;
    const int z = blockIdx.y;
    const int wid = threadIdx.x >> 5;
    const int lane = threadIdx.x & 31;
    const float4* wrow = (const float4*)(fc_w + (size_t)c * (NDIM * NPOOL) + z * 2500);

    for (int b = wid; b < BDIM; b += 4) {
        const float4* pr = (const float4*)(g_pool + (size_t)b * (NDIM * NPOOL) + z * 2500);
        float acc = 0.f;
        for (int k = lane; k < 625; k += 32) {   // 2500/4
            float4 w4 = wrow[k];
            float4 p4 = pr[k];
            acc += w4.x * p4.x + w4.y * p4.y + w4.z * p4.z + w4.w * p4.w;
        }
        #pragma unroll
        for (int off = 16; off > 0; off >>= 1)
            acc += __shfl_xor_sync(0xFFFFFFFFu, acc, off);
        if (lane == 0) g_fcp[z][b][c] = acc;
    }
}

// =====================================================================
// Kernel 3b: finalize logits (3328 outputs)
// =====================================================================
__global__ void __launch_bounds__(256) fc_final_kernel(const float* __restrict__ fc_b,
                                                       float* __restrict__ out) {
    const int i = blockIdx.x * blockDim.x + threadIdx.x;
    if (i >= BDIM * CDIM) return;
    const int b = i / CDIM;
    const int c = i % CDIM;
    const float ss = g_ss[b * 4 + 0] + g_ss[b * 4 + 1] + g_ss[b * 4 + 2] + g_ss[b * 4 + 3];
    const float dot = g_fcp[0][b][c] + g_fcp[1][b][c] + g_fcp[2][b][c] + g_fcp[3][b][c];
    out[i] = fc_b[c] + rsqrtf(1.0f + ss) * dot;
}

// =====================================================================
extern "C" void kernel_launch(void* const* d_in, const int* in_sizes, int n_in,
                              void* d_out, int out_size) {
    const float* x      = (const float*)d_in[0];  // [32,100,30000]
    const float* conv_w = (const float*)d_in[1];  // [1000,30000]
    const float* conv_b = (const float*)d_in[2];  // [1000]
    const float* fc_w   = (const float*)d_in[3];  // [104,10000]
    const float* fc_b   = (const float*)d_in[4];  // [104]
    float* out = (float*)d_out;                   // [32,104]

    static int configured = 0;
    if (!configured) {
        cudaFuncSetAttribute(gemm_kernel,
                             cudaFuncAttributeMaxDynamicSharedMemorySize, SMEM_BYTES);
        configured = 1;
    }

    __half* xh; cudaGetSymbolAddress((void**)&xh, g_xh);
    __half* wh; cudaGetSymbolAddress((void**)&wh, g_wh);

    convert_kernel<<<2048, 256>>>(x, xh, (MDIM * KDIM) / 8);
    convert_kernel<<<1024, 256>>>(conv_w, wh, (NDIM * KDIM) / 8);
    gemm_kernel<<<dim3(MDIM / MT, 8, KSPLIT), 128, SMEM_BYTES>>>();
    pool_norm_kernel<<<dim3(4, BDIM), 256>>>(conv_b);
    fc_partial_kernel<<<dim3(CDIM, 4), 128>>>(fc_w);
    fc_final_kernel<<<(BDIM * CDIM + 255) / 256, 256>>>(fc_b, out);
}